// round 12
// baseline (speedup 1.0000x reference)
#include <cuda_runtime.h>
#include <cuda_bf16.h>
#include <cstddef>

// Shapes: user [B=32, U=128, D=256] fp32, image [B=32, I=256, D=256] fp32
// out = concat(user * img_sum[b,1,:], image * user_sum[b,1,:])
//
// R11 structure (best: 7.71us ncu) with 256-bit vector memory ops:
// 6 x ld.global.nc.v8.f32 + 6 x st.global.cs.v8.f32 per thread instead of
// 12+12 128-bit ops. Same 24MB traffic, same full-line coalescing (warp
// row-group = 8 x 128B lines), half the L1tex wavefront queue entries.

#define BB 32
#define UU 128
#define II 256
#define DD 256

#define TX 4                 // float8 lanes: 32 floats = 128B per 4-lane seg
#define TY 64                // row groups
#define NT (TX * TY)         // 256 threads
#define DCH 32               // d-chunk per CTA
#define NCH (DD / DCH)       // 8
#define GRID (BB * NCH)      // 256
#define NWARPS (NT / 32)     // 8

struct f8 { float4 a, b; };

__device__ __forceinline__ f8 f8add(f8 x, f8 y) {
    f8 r;
    r.a = make_float4(x.a.x + y.a.x, x.a.y + y.a.y, x.a.z + y.a.z, x.a.w + y.a.w);
    r.b = make_float4(x.b.x + y.b.x, x.b.y + y.b.y, x.b.z + y.b.z, x.b.w + y.b.w);
    return r;
}
__device__ __forceinline__ f8 f8mul(f8 x, f8 y) {
    f8 r;
    r.a = make_float4(x.a.x * y.a.x, x.a.y * y.a.y, x.a.z * y.a.z, x.a.w * y.a.w);
    r.b = make_float4(x.b.x * y.b.x, x.b.y * y.b.y, x.b.z * y.b.z, x.b.w * y.b.w);
    return r;
}
__device__ __forceinline__ void f8shfl_acc(f8& v, int m) {
    v.a.x += __shfl_xor_sync(0xffffffffu, v.a.x, m);
    v.a.y += __shfl_xor_sync(0xffffffffu, v.a.y, m);
    v.a.z += __shfl_xor_sync(0xffffffffu, v.a.z, m);
    v.a.w += __shfl_xor_sync(0xffffffffu, v.a.w, m);
    v.b.x += __shfl_xor_sync(0xffffffffu, v.b.x, m);
    v.b.y += __shfl_xor_sync(0xffffffffu, v.b.y, m);
    v.b.z += __shfl_xor_sync(0xffffffffu, v.b.z, m);
    v.b.w += __shfl_xor_sync(0xffffffffu, v.b.w, m);
}
__device__ __forceinline__ f8 ldg_nc8(const float* p) {
    f8 v;
    asm volatile("ld.global.nc.v8.f32 {%0,%1,%2,%3,%4,%5,%6,%7}, [%8];"
                 : "=f"(v.a.x), "=f"(v.a.y), "=f"(v.a.z), "=f"(v.a.w),
                   "=f"(v.b.x), "=f"(v.b.y), "=f"(v.b.z), "=f"(v.b.w)
                 : "l"(p));
    return v;
}
__device__ __forceinline__ void stg_cs8(float* p, f8 v) {
    asm volatile("st.global.cs.v8.f32 [%0], {%1,%2,%3,%4,%5,%6,%7,%8};"
                 :: "l"(p),
                    "f"(v.a.x), "f"(v.a.y), "f"(v.a.z), "f"(v.a.w),
                    "f"(v.b.x), "f"(v.b.y), "f"(v.b.z), "f"(v.b.w)
                 : "memory");
}

__global__ __launch_bounds__(NT)
void ExternalInteraction_65609920413984_kernel(
    const float* __restrict__ user,
    const float* __restrict__ img,
    float* __restrict__ out_user,
    float* __restrict__ out_img)
{
    __shared__ f8 wsI[NWARPS][TX];
    __shared__ f8 wsU[NWARPS][TX];

    const int b  = blockIdx.x >> 3;               // / NCH
    const int d0 = (blockIdx.x & (NCH - 1)) * DCH;
    const int tx = threadIdx.x & (TX - 1);        // 0..3
    const int ty = threadIdx.x >> 2;              // 0..63
    const int warp = threadIdx.x >> 5;
    const int lane = threadIdx.x & 31;
    const int d  = d0 + tx * 8;

    const float* up = user + (size_t)b * UU * DD + d;
    const float* ip = img  + (size_t)b * II * DD + d;
    float* ou = out_user + (size_t)b * UU * DD + d;
    float* oi = out_img  + (size_t)b * II * DD + d;

    // ---- Phase A: all loads up front (6 independent 32B loads / thread) ----
    f8 iv[II / TY];   // 4
    f8 uv[UU / TY];   // 2
    #pragma unroll
    for (int k = 0; k < II / TY; k++)
        iv[k] = ldg_nc8(ip + (size_t)(ty + k * TY) * DD);
    #pragma unroll
    for (int k = 0; k < UU / TY; k++)
        uv[k] = ldg_nc8(up + (size_t)(ty + k * TY) * DD);

    // ---- Phase B: both column sums ----
    f8 ai = f8add(f8add(iv[0], iv[1]), f8add(iv[2], iv[3]));
    f8 au = f8add(uv[0], uv[1]);

    // intra-warp: 8 ty-subrows share each tx (ty bits = lane bits 2,3,4)
    f8shfl_acc(ai, 4);  f8shfl_acc(ai, 8);  f8shfl_acc(ai, 16);
    f8shfl_acc(au, 4);  f8shfl_acc(au, 8);  f8shfl_acc(au, 16);

    if (lane < TX) { wsI[warp][tx] = ai; wsU[warp][tx] = au; }
    __syncthreads();                       // the ONLY barrier

    f8 is = wsI[0][tx];
    f8 us = wsU[0][tx];
    #pragma unroll
    for (int w = 1; w < NWARPS; w++) {
        is = f8add(is, wsI[w][tx]);
        us = f8add(us, wsU[w][tx]);
    }

    // ---- Phase C: stores from registers (streaming, evict-first) ----
    #pragma unroll
    for (int k = 0; k < UU / TY; k++)
        stg_cs8(ou + (size_t)(ty + k * TY) * DD, f8mul(uv[k], is));
    #pragma unroll
    for (int k = 0; k < II / TY; k++)
        stg_cs8(oi + (size_t)(ty + k * TY) * DD, f8mul(iv[k], us));
}

extern "C" void kernel_launch(void* const* d_in, const int* in_sizes, int n_in,
                              void* d_out, int out_size)
{
    (void)in_sizes; (void)n_in; (void)out_size;
    const float* user = (const float*)d_in[0];
    const float* img  = (const float*)d_in[1];
    float* out_user = (float*)d_out;
    float* out_img  = (float*)d_out + (size_t)BB * UU * DD;

    ExternalInteraction_65609920413984_kernel
        <<<GRID, NT>>>(user, img, out_user, out_img);
}